// round 3
// baseline (speedup 1.0000x reference)
#include <cuda_runtime.h>
#include <math.h>

// Shapes (fixed by the problem)
//  x       [16][16][4096]
//  conv_w  [256][16][9]
//  conv_b  [256]
//  caps_w  [8][16][256]
//  caps_b  [8][16]
//  W       [8][16][16]
//  out     [8][16][8][4096]  (n0, k, n, s)

__device__ float g_C[8 * 16 * 16];        // [n0][k][b]
__device__ float g_Weff[128 * 144];       // [nk = n*16+k][ic*9+dk]
__device__ float g_beff[128];             // [nk = n*16+k]
__device__ float g_u[16 * 128 * 4096];    // [b][kn = k*8+n][s]

// ---------------------------------------------------------------------------
// K0: softmax rows of W (over IC axis) and effective bias
// ---------------------------------------------------------------------------
__global__ void k_setup(const float* __restrict__ Wr,
                        const float* __restrict__ caps_w,
                        const float* __restrict__ conv_b,
                        const float* __restrict__ caps_b) {
    int t = threadIdx.x;
    if (t < 128) {
        // softmax over b of W[n0][b][k]
        int n0 = t >> 4, k = t & 15;
        float m = -1e30f;
        float e[16];
        #pragma unroll
        for (int b = 0; b < 16; b++) {
            float w = Wr[(n0 * 16 + b) * 16 + k];
            m = fmaxf(m, w);
        }
        float sum = 0.f;
        #pragma unroll
        for (int b = 0; b < 16; b++) {
            float v = expf(Wr[(n0 * 16 + b) * 16 + k] - m);
            e[b] = v;
            sum += v;
        }
        float inv = 1.f / sum;
        #pragma unroll
        for (int b = 0; b < 16; b++)
            g_C[(n0 * 16 + k) * 16 + b] = e[b] * inv;

        // beff[nk] = sum_oc caps_w[nk][oc] * conv_b[oc] + caps_b[nk]
        float acc = caps_b[t];
        for (int oc = 0; oc < 256; oc++)
            acc += caps_w[t * 256 + oc] * conv_b[oc];
        g_beff[t] = acc;
    }
}

// ---------------------------------------------------------------------------
// K0b: Weff[nk][ic*9+dk] = sum_oc caps_w[nk][oc] * conv_w[oc][ic][dk]
// one block per nk
// ---------------------------------------------------------------------------
__global__ void k_weff(const float* __restrict__ caps_w,
                       const float* __restrict__ conv_w) {
    int nk = blockIdx.x;
    __shared__ float cw[256];
    for (int i = threadIdx.x; i < 256; i += blockDim.x)
        cw[i] = caps_w[nk * 256 + i];
    __syncthreads();
    int t = threadIdx.x;
    if (t < 144) {
        int ic = t / 9, dk = t - ic * 9;
        float acc = 0.f;
        for (int oc = 0; oc < 256; oc++)
            acc += cw[oc] * conv_w[(oc * 16 + ic) * 9 + dk];
        g_Weff[nk * 144 + t] = acc;
    }
}

// ---------------------------------------------------------------------------
// K1: u[b][kn][s] = sum_{ic,dk} Weff[nk][ic*9+dk] * x[b][ic][s+dk-4] + beff
// grid: (s-tile 16, b 16); block 128 threads (thread = kn = k*8+n)
// ---------------------------------------------------------------------------
__global__ __launch_bounds__(128, 2) void k_conv(const float* __restrict__ x) {
    const int b   = blockIdx.y;
    const int s0  = blockIdx.x * 256;
    const int tid = threadIdx.x;                 // kn
    const int k = tid >> 3, n = tid & 7;
    const int nk = n * 16 + k;

    __shared__ __align__(16) float xs[16][264];  // x[b][ic][s0-4 .. s0+259]

    for (int j = tid; j < 16 * 264; j += 128) {
        int ic = j / 264, jj = j - ic * 264;
        int s = s0 - 4 + jj;
        xs[ic][jj] = (s >= 0 && s < 4096) ? x[(b * 16 + ic) * 4096 + s] : 0.f;
    }

    float w[144];
    #pragma unroll
    for (int i = 0; i < 144; i++) w[i] = g_Weff[nk * 144 + i];
    const float bv = g_beff[nk];
    __syncthreads();

    float* uout = &g_u[(b * 128 + tid) * 4096 + s0];

    for (int c = 0; c < 32; c++) {
        const int sb = c * 8;
        float acc[8];
        #pragma unroll
        for (int t2 = 0; t2 < 8; t2++) acc[t2] = bv;

        #pragma unroll
        for (int ic = 0; ic < 16; ic++) {
            float xv[16];
            #pragma unroll
            for (int q = 0; q < 4; q++) {
                float4 v4 = *reinterpret_cast<const float4*>(&xs[ic][sb + q * 4]);
                xv[q * 4 + 0] = v4.x; xv[q * 4 + 1] = v4.y;
                xv[q * 4 + 2] = v4.z; xv[q * 4 + 3] = v4.w;
            }
            #pragma unroll
            for (int dk = 0; dk < 9; dk++) {
                float wv = w[ic * 9 + dk];
                #pragma unroll
                for (int t2 = 0; t2 < 8; t2++)
                    acc[t2] = fmaf(wv, xv[t2 + dk], acc[t2]);
            }
        }
        *reinterpret_cast<float4*>(&uout[sb])     = make_float4(acc[0], acc[1], acc[2], acc[3]);
        *reinterpret_cast<float4*>(&uout[sb + 4]) = make_float4(acc[4], acc[5], acc[6], acc[7]);
    }
}

// ---------------------------------------------------------------------------
// K2: routing. one block per (n0, kn). 256 threads.
//  s0[s] = sum_b C[n0][k][b] * u[b][kn][s];  U[s] = sum_b u[b][kn][s]
//  f(SS) = sqrt(SS)/(1+SS)
//  s1 = s0*(1 + f0*s0*U);  s2 = s0 + f1*s1*s1*U;  out = f2*s2
// ---------------------------------------------------------------------------
__device__ __forceinline__ float block_reduce(float p, float* red, int tid) {
    #pragma unroll
    for (int o = 16; o > 0; o >>= 1)
        p += __shfl_xor_sync(0xffffffffu, p, o);
    __syncthreads();                 // protect red[] reuse across calls
    if ((tid & 31) == 0) red[tid >> 5] = p;
    __syncthreads();
    if (tid == 0) {
        float s = 0.f;
        #pragma unroll
        for (int i = 0; i < 8; i++) s += red[i];
        red[8] = s;
    }
    __syncthreads();
    return red[8];
}

__global__ __launch_bounds__(256) void k_routing(float* __restrict__ out) {
    const int bid = blockIdx.x;
    const int n0 = bid >> 7, kn = bid & 127;
    const int k = kn >> 3;
    const int tid = threadIdx.x;

    __shared__ float s0s[4096];
    __shared__ float Us[4096];
    __shared__ float red[9];

    float c[16];
    #pragma unroll
    for (int b = 0; b < 16; b++) c[b] = g_C[(n0 * 16 + k) * 16 + b];

    for (int s = tid; s < 4096; s += 256) {
        float U = 0.f, S = 0.f;
        #pragma unroll
        for (int b = 0; b < 16; b++) {
            float v = g_u[(b * 128 + kn) * 4096 + s];
            U += v;
            S = fmaf(c[b], v, S);
        }
        s0s[s] = S;
        Us[s] = U;
    }
    __syncthreads();

    float p, SS;

    // SS0
    p = 0.f;
    for (int s = tid; s < 4096; s += 256) { float v = s0s[s]; p = fmaf(v, v, p); }
    SS = block_reduce(p, red, tid);
    const float f0 = sqrtf(SS) / (1.f + SS);

    // SS1
    p = 0.f;
    for (int s = tid; s < 4096; s += 256) {
        float a = s0s[s], Uv = Us[s];
        float s1 = a * (1.f + f0 * a * Uv);
        p = fmaf(s1, s1, p);
    }
    SS = block_reduce(p, red, tid);
    const float f1 = sqrtf(SS) / (1.f + SS);

    // SS2
    p = 0.f;
    for (int s = tid; s < 4096; s += 256) {
        float a = s0s[s], Uv = Us[s];
        float s1 = a * (1.f + f0 * a * Uv);
        float s2 = a + f1 * s1 * s1 * Uv;
        p = fmaf(s2, s2, p);
    }
    SS = block_reduce(p, red, tid);
    const float f2 = sqrtf(SS) / (1.f + SS);

    float* orow = out + bid * 4096;   // bid == ((n0*16+k)*8+n)
    for (int s = tid; s < 4096; s += 256) {
        float a = s0s[s], Uv = Us[s];
        float s1 = a * (1.f + f0 * a * Uv);
        float s2 = a + f1 * s1 * s1 * Uv;
        orow[s] = f2 * s2;
    }
}

// ---------------------------------------------------------------------------
extern "C" void kernel_launch(void* const* d_in, const int* in_sizes, int n_in,
                              void* d_out, int out_size) {
    const float* x      = (const float*)d_in[0];
    const float* conv_w = (const float*)d_in[1];
    const float* conv_b = (const float*)d_in[2];
    const float* caps_w = (const float*)d_in[3];
    const float* caps_b = (const float*)d_in[4];
    const float* W      = (const float*)d_in[5];
    float* out = (float*)d_out;

    k_setup<<<1, 128>>>(W, caps_w, conv_b, caps_b);
    k_weff<<<128, 160>>>(caps_w, conv_w);
    k_conv<<<dim3(16, 16), 128>>>(x);
    k_routing<<<1024, 256>>>(out);
}